// round 15
// baseline (speedup 1.0000x reference)
#include <cuda_runtime.h>
#include <cuda_fp16.h>
#include <cstdint>
#include <cstddef>

#define Bb 4
#define Tt 4096
#define Hh 16
#define DKk 64
#define DVv 64
#define Mrows (Bb*Tt)          // 16384
#define NCOL 1024
#define KDIM 1024
#define EPSF 1e-6f
#define KVSPLIT 16
#define TSEG (Tt/KVSPLIT)      // 256

// ---------------- static scratch ----------------
__device__ __half g_Xin[3][(size_t)Mrows*KDIM];   // fp16 inputs (q,k,v source)
__device__ __half g_Qh[(size_t)Mrows*NCOL];       // fp16 projected Q (phi applied)
__device__ __half g_Kh[(size_t)Mrows*NCOL];
__device__ __half g_Vh[(size_t)Mrows*NCOL];
__device__ __half g_At[(size_t)Mrows*NCOL];       // fp16 attn output (final GEMM input)
__device__ __half g_Whi[4][(size_t)NCOL*KDIM];    // transposed [N,K], fp16
__device__ float g_kvp[KVSPLIT*64*DVv*DKk];
__device__ float g_ksp[KVSPLIT*64*DKk];
__device__ __half g_kvh[64*DVv*DKk];              // fp16 kv (attn GEMM B operand)
__device__ float g_ksum[64*DKk];

// ---------------- PTX helpers (baseline ISA: sm_80 features only) -----------
__device__ __forceinline__ uint32_t s2u(const void* p){
    uint32_t a;
    asm("{ .reg .u64 t; cvta.to.shared.u64 t, %1; cvt.u32.u64 %0, t; }" : "=r"(a) : "l"(p));
    return a;
}
__device__ __forceinline__ void cpa16(uint32_t dst, const void* src){
    asm volatile("cp.async.cg.shared.global [%0], [%1], 16;" :: "r"(dst), "l"(src) : "memory");
}
__device__ __forceinline__ void cp_commit(){
    asm volatile("cp.async.commit_group;" ::: "memory");
}
template<int N>
__device__ __forceinline__ void cp_waitg(){
    asm volatile("cp.async.wait_group %0;" :: "n"(N) : "memory");
}
__device__ __forceinline__ void ldm4(uint32_t* r, uint32_t addr){
    asm volatile("ldmatrix.sync.aligned.m8n8.x4.shared.b16 {%0,%1,%2,%3}, [%4];"
        : "=r"(r[0]), "=r"(r[1]), "=r"(r[2]), "=r"(r[3]) : "r"(addr));
}
__device__ __forceinline__ void ldm4t(uint32_t* r, uint32_t addr){
    asm volatile("ldmatrix.sync.aligned.m8n8.x4.trans.shared.b16 {%0,%1,%2,%3}, [%4];"
        : "=r"(r[0]), "=r"(r[1]), "=r"(r[2]), "=r"(r[3]) : "r"(addr));
}
__device__ __forceinline__ void mma16816(float* c, const uint32_t* a, uint32_t b0, uint32_t b1){
    asm volatile("mma.sync.aligned.m16n8k16.row.col.f32.f16.f16.f32 "
        "{%0,%1,%2,%3}, {%4,%5,%6,%7}, {%8,%9}, {%0,%1,%2,%3};"
        : "+f"(c[0]), "+f"(c[1]), "+f"(c[2]), "+f"(c[3])
        : "r"(a[0]), "r"(a[1]), "r"(a[2]), "r"(a[3]), "r"(b0), "r"(b1));
}

// ---------------- HMMA GEMM tile (1-pass): C = act(A @ W^T + bias) ----------
// Tile 128x128, k-chunk 32, 3-stage cp.async pipeline, 2 CTAs/SM.
// Invoked from persistent loops. Cross-tile smem safety: prologue writes
// stages 0..1 whose last readers finished before the previous tile's final
// barriers; stage 2 is first overwritten only after a fresh __syncthreads.
#define RSTRIDE 80                 // bytes per 32-half row
#define TILE_SM (128*RSTRIDE)      // 10240 bytes per [128][32] tile
#define NKCH (KDIM/32)             // 32 k-chunks
#define NSTG 3
#define STGB (2*TILE_SM)
#define SMEM_G (NSTG*STGB)         // 61440 -> 2 CTAs/SM

template<int OUT16>
__device__ __forceinline__ void gemm_tile(
    const __half* __restrict__ A, const __half* __restrict__ W,
    const float* __restrict__ bias, void* __restrict__ Cv,
    int act, uint32_t sb, int bm, int bn)
{
    const int tid  = threadIdx.x;
    const int warp = tid >> 5, lane = tid & 31;
    const int wm = warp & 3, wn = warp >> 2;

    const int lrow = tid >> 1;
    const int lc   = (tid & 1) * 2;

    const __half* gA = A + (size_t)(bm + lrow) * KDIM + lc * 8;
    const __half* gB = W + (size_t)(bn + lrow) * KDIM + lc * 8;
    const uint32_t dofs = lrow * RSTRIDE + lc * 16;

    float acc[2][8][4];
#pragma unroll
    for (int i = 0; i < 2; i++)
#pragma unroll
        for (int j = 0; j < 8; j++)
#pragma unroll
            for (int q = 0; q < 4; q++) acc[i][j][q] = 0.f;

#define ISSUE(kt, s) do {                                   \
        uint32_t st_ = sb + (s) * STGB + dofs;              \
        int ko_ = (kt) * 32;                                \
        cpa16(st_,                gA + ko_);                \
        cpa16(st_ + 16,           gA + ko_ + 8);            \
        cpa16(st_ + TILE_SM,      gB + ko_);                \
        cpa16(st_ + TILE_SM + 16, gB + ko_ + 8);            \
    } while (0)

#pragma unroll
    for (int s = 0; s < NSTG - 1; s++) { ISSUE(s, s); cp_commit(); }

    const int lm = lane & 15, lh = lane >> 4;

    for (int kt = 0; kt < NKCH; kt++) {
        cp_waitg<NSTG - 2>();
        __syncthreads();
        if (kt + NSTG - 1 < NKCH) ISSUE(kt + NSTG - 1, (kt + NSTG - 1) % NSTG);
        cp_commit();

        const uint32_t st = sb + (kt % NSTG) * STGB;
#pragma unroll
        for (int kk = 0; kk < 2; kk++) {
            const uint32_t kcol = kk * 32 + lh * 16;
            uint32_t ah[2][4], bh[4][4];
#pragma unroll
            for (int mt = 0; mt < 2; mt++) {
                uint32_t r = (uint32_t)(wm * 32 + mt * 16 + lm);
                ldm4(ah[mt], st + r * RSTRIDE + kcol);
            }
#pragma unroll
            for (int g = 0; g < 4; g++) {
                uint32_t r = (uint32_t)(wn * 64 + g * 16 + lm);
                ldm4(bh[g], st + TILE_SM + r * RSTRIDE + kcol);
            }
#pragma unroll
            for (int mt = 0; mt < 2; mt++)
#pragma unroll
                for (int g = 0; g < 4; g++) {
                    mma16816(acc[mt][2*g],   ah[mt], bh[g][0], bh[g][2]);
                    mma16816(acc[mt][2*g+1], ah[mt], bh[g][1], bh[g][3]);
                }
        }
    }
#undef ISSUE

#pragma unroll
    for (int mt = 0; mt < 2; mt++) {
        const int row0 = bm + wm * 32 + mt * 16 + (lane >> 2);
#pragma unroll
        for (int ng = 0; ng < 8; ng++) {
            const int col = bn + wn * 64 + ng * 8 + 2 * (lane & 3);
            const float b0 = bias[col], b1 = bias[col + 1];
            float2 v0, v1;
            v0.x = acc[mt][ng][0] + b0;  v0.y = acc[mt][ng][1] + b1;
            v1.x = acc[mt][ng][2] + b0;  v1.y = acc[mt][ng][3] + b1;
            if (act) {
                v0.x = v0.x > 0.f ? v0.x + 1.f : __expf(v0.x);
                v0.y = v0.y > 0.f ? v0.y + 1.f : __expf(v0.y);
                v1.x = v1.x > 0.f ? v1.x + 1.f : __expf(v1.x);
                v1.y = v1.y > 0.f ? v1.y + 1.f : __expf(v1.y);
            }
            if (OUT16) {
                __half* C = (__half*)Cv;
                *(__half2*)&C[(size_t)row0 * NCOL + col] =
                    __halves2half2(__float2half(v0.x), __float2half(v0.y));
                *(__half2*)&C[(size_t)(row0 + 8) * NCOL + col] =
                    __halves2half2(__float2half(v1.x), __float2half(v1.y));
            } else {
                float* C = (float*)Cv;
                *(float2*)&C[(size_t)row0 * NCOL + col]       = v0;
                *(float2*)&C[(size_t)(row0 + 8) * NCOL + col] = v1;
            }
        }
    }
}

// persistent QKV projections: 3*1024 tiles over gridDim.x CTAs
__global__ void __launch_bounds__(256, 2) gemm_qkv_p(
    const __half* __restrict__ Xin, const __half* __restrict__ Wt,
    const float* __restrict__ bq, const float* __restrict__ bk, const float* __restrict__ bv,
    __half* __restrict__ Qh, __half* __restrict__ Kh, __half* __restrict__ Vh)
{
    extern __shared__ __align__(128) char smem[];
    const uint32_t sb = s2u(smem);
    for (int t = blockIdx.x; t < 3072; t += gridDim.x) {
        const int z  = t >> 10;
        const int rr = t & 1023;
        const int bn = (rr & 7) * 128;
        const int bm = (rr >> 3) * 128;
        const __half* A = Xin + (size_t)z * Mrows * KDIM;
        const __half* W = Wt  + (size_t)z * NCOL * KDIM;
        const float* bias = (z == 0) ? bq : (z == 1) ? bk : bv;
        __half* C = (z == 0) ? Qh : (z == 1) ? Kh : Vh;
        gemm_tile<1>(A, W, bias, C, (z < 2) ? 1 : 0, sb, bm, bn);
    }
}

// persistent output GEMM: 1024 tiles
__global__ void __launch_bounds__(256, 2) gemm_out_p(
    const __half* __restrict__ A, const __half* __restrict__ W,
    const float* __restrict__ bias, float* __restrict__ C)
{
    extern __shared__ __align__(128) char smem[];
    const uint32_t sb = s2u(smem);
    for (int t = blockIdx.x; t < 1024; t += gridDim.x) {
        const int bn = (t & 7) * 128;
        const int bm = (t >> 3) * 128;
        gemm_tile<0>(A, W, bias, C, 0, sb, bm, bn);
    }
}

// ---------------- merged prep: weight transpose+fp16  AND  input fp32->fp16 -
// blocks [0, 4096): wsplit tiles; blocks [4096, 53248): aconv float4 chunks
__global__ void __launch_bounds__(256) prep_all(
    const float* __restrict__ W0, const float* __restrict__ W1,
    const float* __restrict__ W2, const float* __restrict__ W3,
    __half* __restrict__ Wdst,
    const float* __restrict__ q, const float* __restrict__ k,
    const float* __restrict__ v, __half* __restrict__ Xin)
{
    const int bid = blockIdx.x;
    if (bid < 4096) {
        const int wsel = bid >> 10;
        const int rr   = bid & 1023;
        const int n0 = (rr & 31) * 32, k0 = (rr >> 5) * 32;
        const float* W = (wsel == 0) ? W0 : (wsel == 1) ? W1 : (wsel == 2) ? W2 : W3;
        __half* thi = Wdst + (size_t)wsel * NCOL * KDIM;

        __shared__ float tile[32][33];
        const int tx = threadIdx.x & 31, ty = threadIdx.x >> 5;
#pragma unroll
        for (int r = ty; r < 32; r += 8)
            tile[r][tx] = W[(size_t)(k0 + r) * NCOL + n0 + tx];
        __syncthreads();
#pragma unroll
        for (int r = ty; r < 32; r += 8)
            thi[(size_t)(n0 + r) * KDIM + k0 + tx] = __float2half(tile[tx][r]);
    } else {
        const int n4 = Mrows * KDIM / 4;          // 4194304 float4s per input
        const int b2 = bid - 4096;
        const int z  = b2 >> 14;                  // 16384 blocks per input
        const int i  = (b2 & 16383) * 256 + threadIdx.x;
        if (i >= n4) return;
        const float* src = (z == 0) ? q : (z == 1) ? k : v;
        __half* d = Xin + (size_t)z * Mrows * KDIM;
        float4 val = ((const float4*)src)[i];
        __half2* H = (__half2*)d;
        H[2*i]   = __halves2half2(__float2half(val.x), __float2half(val.y));
        H[2*i+1] = __halves2half2(__float2half(val.z), __float2half(val.w));
    }
}

// ---------------- kv via tensor cores: kv[dv,dk] = sum_t V[t,dv] K[t,dk] ----
#define KVROW 144
#define KVTILE (32*KVROW)          // 4608 bytes per 32x64 fp16 tile

__global__ void __launch_bounds__(128) kv_mma(const __half* __restrict__ Kq,
                                              const __half* __restrict__ Vq,
                                              float* __restrict__ kvp, float* __restrict__ ksp)
{
    __shared__ __align__(16) char sm[2 * 2 * KVTILE];   // [stage][K,V]
    const uint32_t sb = s2u(sm);
    const int bh = blockIdx.x, sp = blockIdx.y;
    const int b = bh >> 4, hd = bh & 15;
    const int tid = threadIdx.x, warp = tid >> 5, lane = tid & 31;

    const __half* Kb = Kq + ((size_t)b * Tt + sp * TSEG) * NCOL + hd * DKk;
    const __half* Vb = Vq + ((size_t)b * Tt + sp * TSEG) * NCOL + hd * DVv;

    float acc[8][4];
#pragma unroll
    for (int j = 0; j < 8; j++)
#pragma unroll
        for (int q = 0; q < 4; q++) acc[j][q] = 0.f;
    float ks = 0.f;

#define KVISSUE(t0, s) do {                                            \
        uint32_t base_ = sb + (s) * (2 * KVTILE);                      \
        _Pragma("unroll")                                              \
        for (int p = 0; p < 2; p++) {                                  \
            int idx_ = tid + p * 128;                                  \
            int r_ = idx_ >> 3, cb_ = idx_ & 7;                        \
            cpa16(base_ + r_ * KVROW + cb_ * 16,                       \
                  Kb + (size_t)((t0) + r_) * NCOL + cb_ * 8);          \
            cpa16(base_ + KVTILE + r_ * KVROW + cb_ * 16,              \
                  Vb + (size_t)((t0) + r_) * NCOL + cb_ * 8);          \
        }                                                              \
    } while (0)

    const int NT = TSEG / 32;   // 8
    KVISSUE(0, 0);  cp_commit();
    KVISSUE(32, 1); cp_commit();

    for (int i = 0; i < NT; i++) {
        if (i == NT - 1) cp_waitg<0>(); else cp_waitg<1>();
        __syncthreads();

        const int s = i & 1;
        const uint32_t Kst = sb + s * (2 * KVTILE);
        const uint32_t Vst = Kst + KVTILE;
#pragma unroll
        for (int kk = 0; kk < 2; kk++) {
            const uint32_t rowoff = (kk * 16 + (lane & 15)) * KVROW + (lane >> 4) * 16;
            uint32_t ar[4];
            ldm4t(ar, Vst + rowoff + warp * 32);          // A = V^T (m=dv,k=t)
            uint32_t a2[4] = { ar[0], ar[2], ar[1], ar[3] };
#pragma unroll
            for (int g = 0; g < 4; g++) {
                uint32_t br[4];
                ldm4t(br, Kst + rowoff + g * 32);          // B = K^T (n=dk,k=t)
                mma16816(acc[2*g],   a2, br[0], br[1]);
                mma16816(acc[2*g+1], a2, br[2], br[3]);
            }
        }
        if (tid < 64) {
#pragma unroll
            for (int t = 0; t < 32; t++)
                ks += __half2float(*(const __half*)(sm + s * (2 * KVTILE) + t * KVROW + tid * 2));
        }
        __syncthreads();
        if (i + 2 < NT) { KVISSUE((i + 2) * 32, s); cp_commit(); }
    }
#undef KVISSUE

    float* o = kvp + (size_t)(sp * 64 + bh) * (DVv * DKk);
    const int r = warp * 16 + (lane >> 2);
    const int c = 2 * (lane & 3);
#pragma unroll
    for (int j = 0; j < 8; j++) {
        const int n0 = (j >> 1) * 16 + (j & 1) * 8 + c;
        float2 lo; lo.x = acc[j][0]; lo.y = acc[j][1];
        float2 hi; hi.x = acc[j][2]; hi.y = acc[j][3];
        *(float2*)&o[r * DKk + n0]       = lo;
        *(float2*)&o[(r + 8) * DKk + n0] = hi;
    }
    if (tid < 64) ksp[(sp * 64 + bh) * DKk + tid] = ks;
}

// reduce partials -> fp16 kv + fp32 ksum. grid (64, 4).
__global__ void __launch_bounds__(256) kv_reduce(const float* __restrict__ kvp, const float* __restrict__ ksp,
                                                 __half* __restrict__ kvh, float* __restrict__ ksum)
{
    const int bh = blockIdx.x, tid = threadIdx.x;
    const int i0 = blockIdx.y * 1024;
    for (int i = i0 + tid; i < i0 + 1024; i += 256) {
        float s = 0.f;
#pragma unroll
        for (int y = 0; y < KVSPLIT; y++) s += kvp[(size_t)(y * 64 + bh) * (DVv * DKk) + i];
        kvh[(size_t)bh * (DVv * DKk) + i] = __float2half(s);
    }
    if (blockIdx.y == 0 && tid < DKk) {
        float s = 0.f;
#pragma unroll
        for (int y = 0; y < KVSPLIT; y++) s += ksp[(y * 64 + bh) * DKk + tid];
        ksum[bh * DKk + tid] = s;
    }
}

// ---------------- attn via tensor cores: attn[t,dv] = nrm * Q[t,:] . kv[dv,:]
__global__ void __launch_bounds__(128) attn_mma(
    const __half* __restrict__ Qq, const __half* __restrict__ kvh,
    const float* __restrict__ ksum, __half* __restrict__ aout)
{
    __shared__ __align__(16) __half Qs[128 * 72];
    __shared__ __align__(16) __half Bs[64 * 72];
    __shared__ float kss[64];
    __shared__ float nrm[128];

    const int bh = blockIdx.x;
    const int b = bh >> 4, hd = bh & 15;
    const int t0 = blockIdx.y * 128;
    const int tid = threadIdx.x, warp = tid >> 5, lane = tid & 31;

    const __half* Qb = Qq + ((size_t)(b * Tt + t0)) * NCOL + hd * DKk;
#pragma unroll
    for (int p = 0; p < 8; p++) {
        int idx = tid + p * 128;
        int r = idx >> 3, cb = idx & 7;
        *(uint4*)&Qs[r * 72 + cb * 8] = *(const uint4*)&Qb[(size_t)r * NCOL + cb * 8];
    }
    const __half* kb = kvh + (size_t)bh * (DVv * DKk);
#pragma unroll
    for (int p = 0; p < 4; p++) {
        int idx = tid + p * 128;
        int r = idx >> 3, cb = idx & 7;
        *(uint4*)&Bs[r * 72 + cb * 8] = *(const uint4*)&kb[r * DKk + cb * 8];
    }
    if (tid < 64) kss[tid] = ksum[bh * DKk + tid];
    __syncthreads();

    {
        float s = 0.f;
#pragma unroll
        for (int d = 0; d < 64; d++) s += __half2float(Qs[tid * 72 + d]) * kss[d];
        nrm[tid] = 1.f / (s + EPSF);
    }

    const uint32_t sq = s2u(Qs), sbv = s2u(Bs);
    float acc[2][8][4];
#pragma unroll
    for (int i = 0; i < 2; i++)
#pragma unroll
        for (int j = 0; j < 8; j++)
#pragma unroll
            for (int q = 0; q < 4; q++) acc[i][j][q] = 0.f;

#pragma unroll
    for (int k0 = 0; k0 < 64; k0 += 16) {
        const uint32_t coloff = (k0 + (lane >> 4) * 8) * 2;
        uint32_t a[2][4];
#pragma unroll
        for (int mt = 0; mt < 2; mt++)
            ldm4(a[mt], sq + (warp * 32 + mt * 16 + (lane & 15)) * 144 + coloff);
#pragma unroll
        for (int g = 0; g < 4; g++) {
            uint32_t br[4];
            ldm4(br, sbv + (g * 16 + (lane & 15)) * 144 + coloff);
#pragma unroll
            for (int mt = 0; mt < 2; mt++) {
                mma16816(acc[mt][2*g],   a[mt], br[0], br[2]);
                mma16816(acc[mt][2*g+1], a[mt], br[1], br[3]);
            }
        }
    }
    __syncthreads();

#pragma unroll
    for (int mt = 0; mt < 2; mt++) {
        const int r = warp * 32 + mt * 16 + (lane >> 2);
        const float n0r = nrm[r], n1r = nrm[r + 8];
        const size_t row0 = ((size_t)(b * Tt + t0 + r)) * NCOL + hd * DVv;
        const size_t row1 = row0 + 8 * NCOL;
#pragma unroll
        for (int j = 0; j < 8; j++) {
            const int n0 = (j >> 1) * 16 + (j & 1) * 8 + 2 * (lane & 3);
            *(__half2*)&aout[row0 + n0] = __halves2half2(
                __float2half(acc[mt][j][0] * n0r), __float2half(acc[mt][j][1] * n0r));
            *(__half2*)&aout[row1 + n0] = __halves2half2(
                __float2half(acc[mt][j][2] * n1r), __float2half(acc[mt][j][3] * n1r));
        }
    }
}

// ---------------- host ----------------
extern "C" void kernel_launch(void* const* d_in, const int* in_sizes, int n_in,
                              void* d_out, int out_size)
{
    (void)in_sizes; (void)n_in; (void)out_size;
    const float* query = (const float*)d_in[0];
    const float* key   = (const float*)d_in[1];
    const float* value = (const float*)d_in[2];
    const float* Wq    = (const float*)d_in[3];
    const float* bq    = (const float*)d_in[4];
    const float* Wk    = (const float*)d_in[5];
    const float* bk    = (const float*)d_in[6];
    const float* Wv    = (const float*)d_in[7];
    const float* bv    = (const float*)d_in[8];
    const float* Wo    = (const float*)d_in[9];
    const float* bo    = (const float*)d_in[10];
    float* out = (float*)d_out;

    __half *Xin, *Qh, *Kh, *Vh, *At, *Wt, *kvh;
    float *kvpp, *kspp, *kss;
    cudaGetSymbolAddress((void**)&Xin, g_Xin);
    cudaGetSymbolAddress((void**)&Qh,  g_Qh);
    cudaGetSymbolAddress((void**)&Kh,  g_Kh);
    cudaGetSymbolAddress((void**)&Vh,  g_Vh);
    cudaGetSymbolAddress((void**)&At,  g_At);
    cudaGetSymbolAddress((void**)&Wt,  g_Whi);
    cudaGetSymbolAddress((void**)&kvh, g_kvh);
    cudaGetSymbolAddress((void**)&kvpp, g_kvp);
    cudaGetSymbolAddress((void**)&kspp, g_ksp);
    cudaGetSymbolAddress((void**)&kss,  g_ksum);

    cudaFuncSetAttribute(gemm_qkv_p, cudaFuncAttributeMaxDynamicSharedMemorySize, SMEM_G);
    cudaFuncSetAttribute(gemm_out_p, cudaFuncAttributeMaxDynamicSharedMemorySize, SMEM_G);

    int nsm = 148;
    cudaDeviceGetAttribute(&nsm, cudaDevAttrMultiProcessorCount, 0);
    const int ngrid = 2 * nsm;   // persistent, 2 CTAs/SM

    const size_t WSZ = (size_t)NCOL * KDIM;

    // merged prep: 4096 wsplit blocks + 3*16384 aconv blocks
    prep_all<<<4096 + 3 * 16384, 256>>>(Wq, Wk, Wv, Wo, Wt, query, key, value, Xin);

    gemm_qkv_p<<<ngrid, 256, SMEM_G>>>(Xin, Wt, bq, bk, bv, Qh, Kh, Vh);

    kv_mma<<<dim3(64, KVSPLIT), 128>>>(Kh, Vh, kvpp, kspp);
    kv_reduce<<<dim3(64, 4), 256>>>(kvpp, kspp, kvh, kss);
    attn_mma<<<dim3(64, Tt / 128), 128>>>(Qh, kvh, kss, At);

    gemm_out_p<<<ngrid, 256, SMEM_G>>>(At, Wt + 3 * WSZ, bo, out);
}

// round 16
// speedup vs baseline: 1.0528x; 1.0528x over previous
#include <cuda_runtime.h>
#include <cuda_fp16.h>
#include <cstdint>
#include <cstddef>

#define Bb 4
#define Tt 4096
#define Hh 16
#define DKk 64
#define DVv 64
#define Mrows (Bb*Tt)          // 16384
#define NCOL 1024
#define KDIM 1024
#define EPSF 1e-6f
#define KVSPLIT 16
#define TSEG (Tt/KVSPLIT)      // 256

// ---------------- static scratch ----------------
__device__ __half g_Xin[3][(size_t)Mrows*KDIM];   // fp16 inputs (q,k,v source)
__device__ __half g_Qh[(size_t)Mrows*NCOL];       // fp16 projected Q (phi applied)
__device__ __half g_Kh[(size_t)Mrows*NCOL];
__device__ __half g_Vh[(size_t)Mrows*NCOL];
__device__ __half g_At[(size_t)Mrows*NCOL];       // fp16 attn output (final GEMM input)
__device__ __half g_Whi[4][(size_t)NCOL*KDIM];    // transposed [N,K], fp16
__device__ float g_kvp[KVSPLIT*64*DVv*DKk];
__device__ float g_ksp[KVSPLIT*64*DKk];
__device__ __half g_kvh[64*DVv*DKk];              // fp16 kv (attn GEMM B operand)
__device__ float g_ksum[64*DKk];

// ---------------- PTX helpers (baseline ISA: sm_80 features only) -----------
__device__ __forceinline__ uint32_t s2u(const void* p){
    uint32_t a;
    asm("{ .reg .u64 t; cvta.to.shared.u64 t, %1; cvt.u32.u64 %0, t; }" : "=r"(a) : "l"(p));
    return a;
}
__device__ __forceinline__ void cpa16(uint32_t dst, const void* src){
    asm volatile("cp.async.cg.shared.global [%0], [%1], 16;" :: "r"(dst), "l"(src) : "memory");
}
__device__ __forceinline__ void cp_commit(){
    asm volatile("cp.async.commit_group;" ::: "memory");
}
template<int N>
__device__ __forceinline__ void cp_waitg(){
    asm volatile("cp.async.wait_group %0;" :: "n"(N) : "memory");
}
__device__ __forceinline__ void ldm4(uint32_t* r, uint32_t addr){
    asm volatile("ldmatrix.sync.aligned.m8n8.x4.shared.b16 {%0,%1,%2,%3}, [%4];"
        : "=r"(r[0]), "=r"(r[1]), "=r"(r[2]), "=r"(r[3]) : "r"(addr));
}
__device__ __forceinline__ void ldm4t(uint32_t* r, uint32_t addr){
    asm volatile("ldmatrix.sync.aligned.m8n8.x4.trans.shared.b16 {%0,%1,%2,%3}, [%4];"
        : "=r"(r[0]), "=r"(r[1]), "=r"(r[2]), "=r"(r[3]) : "r"(addr));
}
__device__ __forceinline__ void mma16816(float* c, const uint32_t* a, uint32_t b0, uint32_t b1){
    asm volatile("mma.sync.aligned.m16n8k16.row.col.f32.f16.f16.f32 "
        "{%0,%1,%2,%3}, {%4,%5,%6,%7}, {%8,%9}, {%0,%1,%2,%3};"
        : "+f"(c[0]), "+f"(c[1]), "+f"(c[2]), "+f"(c[3])
        : "r"(a[0]), "r"(a[1]), "r"(a[2]), "r"(a[3]), "r"(b0), "r"(b1));
}

// ---------------- HMMA GEMM core (1-pass): C = act(A @ W^T + bias) ----------
// Tile 128x128, k-chunk 32, 3-stage cp.async pipeline, 2 CTAs/SM.
// (round-8/14 empirical optimum; classic launch — persistence measured worse)
#define RSTRIDE 80                 // bytes per 32-half row
#define TILE_SM (128*RSTRIDE)      // 10240 bytes per [128][32] tile
#define NKCH (KDIM/32)             // 32 k-chunks
#define NSTG 3
#define STGB (2*TILE_SM)
#define SMEM_G (NSTG*STGB)         // 61440 -> 2 CTAs/SM

template<int OUT16>
__device__ __forceinline__ void gemm_core(
    const __half* __restrict__ A, const __half* __restrict__ W,
    const float* __restrict__ bias, void* __restrict__ Cv,
    int act, char* smem)
{
    const uint32_t sb = s2u(smem);
    const int tid  = threadIdx.x;
    const int warp = tid >> 5, lane = tid & 31;
    const int wm = warp & 3, wn = warp >> 2;
    const int bm = blockIdx.y * 128, bn = blockIdx.x * 128;

    const int lrow = tid >> 1;
    const int lc   = (tid & 1) * 2;

    const __half* gA = A + (size_t)(bm + lrow) * KDIM + lc * 8;
    const __half* gB = W + (size_t)(bn + lrow) * KDIM + lc * 8;
    const uint32_t dofs = lrow * RSTRIDE + lc * 16;

    float acc[2][8][4];
#pragma unroll
    for (int i = 0; i < 2; i++)
#pragma unroll
        for (int j = 0; j < 8; j++)
#pragma unroll
            for (int q = 0; q < 4; q++) acc[i][j][q] = 0.f;

#define ISSUE(kt, s) do {                                   \
        uint32_t st_ = sb + (s) * STGB + dofs;              \
        int ko_ = (kt) * 32;                                \
        cpa16(st_,                gA + ko_);                \
        cpa16(st_ + 16,           gA + ko_ + 8);            \
        cpa16(st_ + TILE_SM,      gB + ko_);                \
        cpa16(st_ + TILE_SM + 16, gB + ko_ + 8);            \
    } while (0)

#pragma unroll
    for (int s = 0; s < NSTG - 1; s++) { ISSUE(s, s); cp_commit(); }

    const int lm = lane & 15, lh = lane >> 4;

    for (int kt = 0; kt < NKCH; kt++) {
        cp_waitg<NSTG - 2>();
        __syncthreads();
        if (kt + NSTG - 1 < NKCH) ISSUE(kt + NSTG - 1, (kt + NSTG - 1) % NSTG);
        cp_commit();

        const uint32_t st = sb + (kt % NSTG) * STGB;
#pragma unroll
        for (int kk = 0; kk < 2; kk++) {
            const uint32_t kcol = kk * 32 + lh * 16;
            uint32_t ah[2][4], bh[4][4];
#pragma unroll
            for (int mt = 0; mt < 2; mt++) {
                uint32_t r = (uint32_t)(wm * 32 + mt * 16 + lm);
                ldm4(ah[mt], st + r * RSTRIDE + kcol);
            }
#pragma unroll
            for (int g = 0; g < 4; g++) {
                uint32_t r = (uint32_t)(wn * 64 + g * 16 + lm);
                ldm4(bh[g], st + TILE_SM + r * RSTRIDE + kcol);
            }
#pragma unroll
            for (int mt = 0; mt < 2; mt++)
#pragma unroll
                for (int g = 0; g < 4; g++) {
                    mma16816(acc[mt][2*g],   ah[mt], bh[g][0], bh[g][2]);
                    mma16816(acc[mt][2*g+1], ah[mt], bh[g][1], bh[g][3]);
                }
        }
    }
#undef ISSUE

#pragma unroll
    for (int mt = 0; mt < 2; mt++) {
        const int row0 = bm + wm * 32 + mt * 16 + (lane >> 2);
#pragma unroll
        for (int ng = 0; ng < 8; ng++) {
            const int col = bn + wn * 64 + ng * 8 + 2 * (lane & 3);
            const float b0 = bias[col], b1 = bias[col + 1];
            float2 v0, v1;
            v0.x = acc[mt][ng][0] + b0;  v0.y = acc[mt][ng][1] + b1;
            v1.x = acc[mt][ng][2] + b0;  v1.y = acc[mt][ng][3] + b1;
            if (act) {
                v0.x = v0.x > 0.f ? v0.x + 1.f : __expf(v0.x);
                v0.y = v0.y > 0.f ? v0.y + 1.f : __expf(v0.y);
                v1.x = v1.x > 0.f ? v1.x + 1.f : __expf(v1.x);
                v1.y = v1.y > 0.f ? v1.y + 1.f : __expf(v1.y);
            }
            if (OUT16) {
                __half* C = (__half*)Cv;
                *(__half2*)&C[(size_t)row0 * NCOL + col] =
                    __halves2half2(__float2half(v0.x), __float2half(v0.y));
                *(__half2*)&C[(size_t)(row0 + 8) * NCOL + col] =
                    __halves2half2(__float2half(v1.x), __float2half(v1.y));
            } else {
                float* C = (float*)Cv;
                *(float2*)&C[(size_t)row0 * NCOL + col]       = v0;
                *(float2*)&C[(size_t)(row0 + 8) * NCOL + col] = v1;
            }
        }
    }
}

__global__ void __launch_bounds__(256, 2) gemm_qkv(
    const __half* __restrict__ Xin, const __half* __restrict__ Wt,
    const float* __restrict__ bq, const float* __restrict__ bk, const float* __restrict__ bv,
    __half* __restrict__ Qh, __half* __restrict__ Kh, __half* __restrict__ Vh)
{
    extern __shared__ __align__(128) char smem[];
    const int z = blockIdx.z;
    const __half* A = Xin + (size_t)z * Mrows * KDIM;
    const __half* W = Wt  + (size_t)z * NCOL * KDIM;
    const float* bias = (z == 0) ? bq : (z == 1) ? bk : bv;
    __half* C = (z == 0) ? Qh : (z == 1) ? Kh : Vh;
    gemm_core<1>(A, W, bias, C, (z < 2) ? 1 : 0, smem);
}

__global__ void __launch_bounds__(256, 2) gemm_out(
    const __half* __restrict__ A, const __half* __restrict__ W,
    const float* __restrict__ bias, float* __restrict__ C)
{
    extern __shared__ __align__(128) char smem[];
    gemm_core<0>(A, W, bias, C, 0, smem);
}

// ---------------- merged prep: weight transpose+fp16  AND  input fp32->fp16 -
// blocks [0, 4096): wsplit tiles; blocks [4096, 53248): aconv float4 chunks
__global__ void __launch_bounds__(256) prep_all(
    const float* __restrict__ W0, const float* __restrict__ W1,
    const float* __restrict__ W2, const float* __restrict__ W3,
    __half* __restrict__ Wdst,
    const float* __restrict__ q, const float* __restrict__ k,
    const float* __restrict__ v, __half* __restrict__ Xin)
{
    const int bid = blockIdx.x;
    if (bid < 4096) {
        const int wsel = bid >> 10;
        const int rr   = bid & 1023;
        const int n0 = (rr & 31) * 32, k0 = (rr >> 5) * 32;
        const float* W = (wsel == 0) ? W0 : (wsel == 1) ? W1 : (wsel == 2) ? W2 : W3;
        __half* thi = Wdst + (size_t)wsel * NCOL * KDIM;

        __shared__ float tile[32][33];
        const int tx = threadIdx.x & 31, ty = threadIdx.x >> 5;
#pragma unroll
        for (int r = ty; r < 32; r += 8)
            tile[r][tx] = W[(size_t)(k0 + r) * NCOL + n0 + tx];
        __syncthreads();
#pragma unroll
        for (int r = ty; r < 32; r += 8)
            thi[(size_t)(n0 + r) * KDIM + k0 + tx] = __float2half(tile[tx][r]);
    } else {
        const int n4 = Mrows * KDIM / 4;          // 4194304 float4s per input
        const int b2 = bid - 4096;
        const int z  = b2 >> 14;                  // 16384 blocks per input
        const int i  = (b2 & 16383) * 256 + threadIdx.x;
        if (i >= n4) return;
        const float* src = (z == 0) ? q : (z == 1) ? k : v;
        __half* d = Xin + (size_t)z * Mrows * KDIM;
        float4 val = ((const float4*)src)[i];
        __half2* H = (__half2*)d;
        H[2*i]   = __halves2half2(__float2half(val.x), __float2half(val.y));
        H[2*i+1] = __halves2half2(__float2half(val.z), __float2half(val.w));
    }
}

// ---------------- kv via tensor cores: kv[dv,dk] = sum_t V[t,dv] K[t,dk] ----
#define KVROW 144
#define KVTILE (32*KVROW)          // 4608 bytes per 32x64 fp16 tile

__global__ void __launch_bounds__(128) kv_mma(const __half* __restrict__ Kq,
                                              const __half* __restrict__ Vq,
                                              float* __restrict__ kvp, float* __restrict__ ksp)
{
    __shared__ __align__(16) char sm[2 * 2 * KVTILE];   // [stage][K,V]
    const uint32_t sb = s2u(sm);
    const int bh = blockIdx.x, sp = blockIdx.y;
    const int b = bh >> 4, hd = bh & 15;
    const int tid = threadIdx.x, warp = tid >> 5, lane = tid & 31;

    const __half* Kb = Kq + ((size_t)b * Tt + sp * TSEG) * NCOL + hd * DKk;
    const __half* Vb = Vq + ((size_t)b * Tt + sp * TSEG) * NCOL + hd * DVv;

    float acc[8][4];
#pragma unroll
    for (int j = 0; j < 8; j++)
#pragma unroll
        for (int q = 0; q < 4; q++) acc[j][q] = 0.f;
    float ks = 0.f;

#define KVISSUE(t0, s) do {                                            \
        uint32_t base_ = sb + (s) * (2 * KVTILE);                      \
        _Pragma("unroll")                                              \
        for (int p = 0; p < 2; p++) {                                  \
            int idx_ = tid + p * 128;                                  \
            int r_ = idx_ >> 3, cb_ = idx_ & 7;                        \
            cpa16(base_ + r_ * KVROW + cb_ * 16,                       \
                  Kb + (size_t)((t0) + r_) * NCOL + cb_ * 8);          \
            cpa16(base_ + KVTILE + r_ * KVROW + cb_ * 16,              \
                  Vb + (size_t)((t0) + r_) * NCOL + cb_ * 8);          \
        }                                                              \
    } while (0)

    const int NT = TSEG / 32;   // 8
    KVISSUE(0, 0);  cp_commit();
    KVISSUE(32, 1); cp_commit();

    for (int i = 0; i < NT; i++) {
        if (i == NT - 1) cp_waitg<0>(); else cp_waitg<1>();
        __syncthreads();

        const int s = i & 1;
        const uint32_t Kst = sb + s * (2 * KVTILE);
        const uint32_t Vst = Kst + KVTILE;
#pragma unroll
        for (int kk = 0; kk < 2; kk++) {
            const uint32_t rowoff = (kk * 16 + (lane & 15)) * KVROW + (lane >> 4) * 16;
            uint32_t ar[4];
            ldm4t(ar, Vst + rowoff + warp * 32);          // A = V^T (m=dv,k=t)
            uint32_t a2[4] = { ar[0], ar[2], ar[1], ar[3] };
#pragma unroll
            for (int g = 0; g < 4; g++) {
                uint32_t br[4];
                ldm4t(br, Kst + rowoff + g * 32);          // B = K^T (n=dk,k=t)
                mma16816(acc[2*g],   a2, br[0], br[1]);
                mma16816(acc[2*g+1], a2, br[2], br[3]);
            }
        }
        if (tid < 64) {
#pragma unroll
            for (int t = 0; t < 32; t++)
                ks += __half2float(*(const __half*)(sm + s * (2 * KVTILE) + t * KVROW + tid * 2));
        }
        __syncthreads();
        if (i + 2 < NT) { KVISSUE((i + 2) * 32, s); cp_commit(); }
    }
#undef KVISSUE

    float* o = kvp + (size_t)(sp * 64 + bh) * (DVv * DKk);
    const int r = warp * 16 + (lane >> 2);
    const int c = 2 * (lane & 3);
#pragma unroll
    for (int j = 0; j < 8; j++) {
        const int n0 = (j >> 1) * 16 + (j & 1) * 8 + c;
        float2 lo; lo.x = acc[j][0]; lo.y = acc[j][1];
        float2 hi; hi.x = acc[j][2]; hi.y = acc[j][3];
        *(float2*)&o[r * DKk + n0]       = lo;
        *(float2*)&o[(r + 8) * DKk + n0] = hi;
    }
    if (tid < 64) ksp[(sp * 64 + bh) * DKk + tid] = ks;
}

// reduce partials -> fp16 kv + fp32 ksum. grid (64, 4).
__global__ void __launch_bounds__(256) kv_reduce(const float* __restrict__ kvp, const float* __restrict__ ksp,
                                                 __half* __restrict__ kvh, float* __restrict__ ksum)
{
    const int bh = blockIdx.x, tid = threadIdx.x;
    const int i0 = blockIdx.y * 1024;
    for (int i = i0 + tid; i < i0 + 1024; i += 256) {
        float s = 0.f;
#pragma unroll
        for (int y = 0; y < KVSPLIT; y++) s += kvp[(size_t)(y * 64 + bh) * (DVv * DKk) + i];
        kvh[(size_t)bh * (DVv * DKk) + i] = __float2half(s);
    }
    if (blockIdx.y == 0 && tid < DKk) {
        float s = 0.f;
#pragma unroll
        for (int y = 0; y < KVSPLIT; y++) s += ksp[(y * 64 + bh) * DKk + tid];
        ksum[bh * DKk + tid] = s;
    }
}

// ---------------- attn via tensor cores: attn[t,dv] = nrm * Q[t,:] . kv[dv,:]
__global__ void __launch_bounds__(128) attn_mma(
    const __half* __restrict__ Qq, const __half* __restrict__ kvh,
    const float* __restrict__ ksum, __half* __restrict__ aout)
{
    __shared__ __align__(16) __half Qs[128 * 72];
    __shared__ __align__(16) __half Bs[64 * 72];
    __shared__ float kss[64];
    __shared__ float nrm[128];

    const int bh = blockIdx.x;
    const int b = bh >> 4, hd = bh & 15;
    const int t0 = blockIdx.y * 128;
    const int tid = threadIdx.x, warp = tid >> 5, lane = tid & 31;

    const __half* Qb = Qq + ((size_t)(b * Tt + t0)) * NCOL + hd * DKk;
#pragma unroll
    for (int p = 0; p < 8; p++) {
        int idx = tid + p * 128;
        int r = idx >> 3, cb = idx & 7;
        *(uint4*)&Qs[r * 72 + cb * 8] = *(const uint4*)&Qb[(size_t)r * NCOL + cb * 8];
    }
    const __half* kb = kvh + (size_t)bh * (DVv * DKk);
#pragma unroll
    for (int p = 0; p < 4; p++) {
        int idx = tid + p * 128;
        int r = idx >> 3, cb = idx & 7;
        *(uint4*)&Bs[r * 72 + cb * 8] = *(const uint4*)&kb[r * DKk + cb * 8];
    }
    if (tid < 64) kss[tid] = ksum[bh * DKk + tid];
    __syncthreads();

    {
        float s = 0.f;
#pragma unroll
        for (int d = 0; d < 64; d++) s += __half2float(Qs[tid * 72 + d]) * kss[d];
        nrm[tid] = 1.f / (s + EPSF);
    }

    const uint32_t sq = s2u(Qs), sbv = s2u(Bs);
    float acc[2][8][4];
#pragma unroll
    for (int i = 0; i < 2; i++)
#pragma unroll
        for (int j = 0; j < 8; j++)
#pragma unroll
            for (int q = 0; q < 4; q++) acc[i][j][q] = 0.f;

#pragma unroll
    for (int k0 = 0; k0 < 64; k0 += 16) {
        const uint32_t coloff = (k0 + (lane >> 4) * 8) * 2;
        uint32_t a[2][4];
#pragma unroll
        for (int mt = 0; mt < 2; mt++)
            ldm4(a[mt], sq + (warp * 32 + mt * 16 + (lane & 15)) * 144 + coloff);
#pragma unroll
        for (int g = 0; g < 4; g++) {
            uint32_t br[4];
            ldm4(br, sbv + (g * 16 + (lane & 15)) * 144 + coloff);
#pragma unroll
            for (int mt = 0; mt < 2; mt++) {
                mma16816(acc[mt][2*g],   a[mt], br[0], br[2]);
                mma16816(acc[mt][2*g+1], a[mt], br[1], br[3]);
            }
        }
    }
    __syncthreads();

#pragma unroll
    for (int mt = 0; mt < 2; mt++) {
        const int r = warp * 32 + mt * 16 + (lane >> 2);
        const float n0r = nrm[r], n1r = nrm[r + 8];
        const size_t row0 = ((size_t)(b * Tt + t0 + r)) * NCOL + hd * DVv;
        const size_t row1 = row0 + 8 * NCOL;
#pragma unroll
        for (int j = 0; j < 8; j++) {
            const int n0 = (j >> 1) * 16 + (j & 1) * 8 + 2 * (lane & 3);
            *(__half2*)&aout[row0 + n0] = __halves2half2(
                __float2half(acc[mt][j][0] * n0r), __float2half(acc[mt][j][1] * n0r));
            *(__half2*)&aout[row1 + n0] = __halves2half2(
                __float2half(acc[mt][j][2] * n1r), __float2half(acc[mt][j][3] * n1r));
        }
    }
}

// ---------------- host ----------------
extern "C" void kernel_launch(void* const* d_in, const int* in_sizes, int n_in,
                              void* d_out, int out_size)
{
    (void)in_sizes; (void)n_in; (void)out_size;
    const float* query = (const float*)d_in[0];
    const float* key   = (const float*)d_in[1];
    const float* value = (const float*)d_in[2];
    const float* Wq    = (const float*)d_in[3];
    const float* bq    = (const float*)d_in[4];
    const float* Wk    = (const float*)d_in[5];
    const float* bk    = (const float*)d_in[6];
    const float* Wv    = (const float*)d_in[7];
    const float* bv    = (const float*)d_in[8];
    const float* Wo    = (const float*)d_in[9];
    const float* bo    = (const float*)d_in[10];
    float* out = (float*)d_out;

    __half *Xin, *Qh, *Kh, *Vh, *At, *Wt, *kvh;
    float *kvpp, *kspp, *kss;
    cudaGetSymbolAddress((void**)&Xin, g_Xin);
    cudaGetSymbolAddress((void**)&Qh,  g_Qh);
    cudaGetSymbolAddress((void**)&Kh,  g_Kh);
    cudaGetSymbolAddress((void**)&Vh,  g_Vh);
    cudaGetSymbolAddress((void**)&At,  g_At);
    cudaGetSymbolAddress((void**)&Wt,  g_Whi);
    cudaGetSymbolAddress((void**)&kvh, g_kvh);
    cudaGetSymbolAddress((void**)&kvpp, g_kvp);
    cudaGetSymbolAddress((void**)&kspp, g_ksp);
    cudaGetSymbolAddress((void**)&kss,  g_ksum);

    cudaFuncSetAttribute(gemm_qkv, cudaFuncAttributeMaxDynamicSharedMemorySize, SMEM_G);
    cudaFuncSetAttribute(gemm_out, cudaFuncAttributeMaxDynamicSharedMemorySize, SMEM_G);

    const size_t WSZ = (size_t)NCOL * KDIM;

    // merged prep: 4096 wsplit blocks + 3*16384 aconv blocks (one launch)
    prep_all<<<4096 + 3 * 16384, 256>>>(Wq, Wk, Wv, Wo, Wt, query, key, value, Xin);

    // QKV projections (classic launch — measured optimum)
    gemm_qkv<<<dim3(NCOL / 128, Mrows / 128, 3), 256, SMEM_G>>>(
        Xin, Wt, bq, bk, bv, Qh, Kh, Vh);

    kv_mma<<<dim3(64, KVSPLIT), 128>>>(Kh, Vh, kvpp, kspp);
    kv_reduce<<<dim3(64, 4), 256>>>(kvpp, kspp, kvh, kss);
    attn_mma<<<dim3(64, Tt / 128), 128>>>(Qh, kvh, kss, At);

    gemm_out<<<dim3(NCOL / 128, Mrows / 128), 256, SMEM_G>>>(At, Wt + 3 * WSZ, bo, out);
}

// round 17
// speedup vs baseline: 1.0554x; 1.0025x over previous
#include <cuda_runtime.h>
#include <cuda_fp16.h>
#include <cstdint>
#include <cstddef>

#define Bb 4
#define Tt 4096
#define Hh 16
#define DKk 64
#define DVv 64
#define Mrows (Bb*Tt)          // 16384
#define NCOL 1024
#define KDIM 1024
#define EPSF 1e-6f
#define KVSPLIT 16
#define TSEG (Tt/KVSPLIT)      // 256

// ---------------- static scratch ----------------
__device__ __half g_Xin[3][(size_t)Mrows*KDIM];   // fp16 inputs (q,k,v source)
__device__ __half g_Qh[(size_t)Mrows*NCOL];       // fp16 projected Q (phi applied)
__device__ __half g_Kh[(size_t)Mrows*NCOL];
__device__ __half g_Vh[(size_t)Mrows*NCOL];
__device__ __half g_At[(size_t)Mrows*NCOL];       // fp16 attn output (final GEMM input)
__device__ __half g_Whi[4][(size_t)NCOL*KDIM];    // transposed [N,K], fp16
__device__ float g_kvp[KVSPLIT*64*DVv*DKk];
__device__ float g_ksp[KVSPLIT*64*DKk];
__device__ __half g_kvh[64*DVv*DKk];              // fp16 kv (attn GEMM B operand)
__device__ float g_ksum[64*DKk];

// ---------------- PTX helpers (baseline ISA: sm_80 features only) -----------
__device__ __forceinline__ uint32_t s2u(const void* p){
    uint32_t a;
    asm("{ .reg .u64 t; cvta.to.shared.u64 t, %1; cvt.u32.u64 %0, t; }" : "=r"(a) : "l"(p));
    return a;
}
__device__ __forceinline__ void cpa16(uint32_t dst, const void* src){
    asm volatile("cp.async.cg.shared.global [%0], [%1], 16;" :: "r"(dst), "l"(src) : "memory");
}
__device__ __forceinline__ void cp_commit(){
    asm volatile("cp.async.commit_group;" ::: "memory");
}
template<int N>
__device__ __forceinline__ void cp_waitg(){
    asm volatile("cp.async.wait_group %0;" :: "n"(N) : "memory");
}
__device__ __forceinline__ void ldm4(uint32_t* r, uint32_t addr){
    asm volatile("ldmatrix.sync.aligned.m8n8.x4.shared.b16 {%0,%1,%2,%3}, [%4];"
        : "=r"(r[0]), "=r"(r[1]), "=r"(r[2]), "=r"(r[3]) : "r"(addr));
}
__device__ __forceinline__ void ldm4t(uint32_t* r, uint32_t addr){
    asm volatile("ldmatrix.sync.aligned.m8n8.x4.trans.shared.b16 {%0,%1,%2,%3}, [%4];"
        : "=r"(r[0]), "=r"(r[1]), "=r"(r[2]), "=r"(r[3]) : "r"(addr));
}
__device__ __forceinline__ void mma16816(float* c, const uint32_t* a, uint32_t b0, uint32_t b1){
    asm volatile("mma.sync.aligned.m16n8k16.row.col.f32.f16.f16.f32 "
        "{%0,%1,%2,%3}, {%4,%5,%6,%7}, {%8,%9}, {%0,%1,%2,%3};"
        : "+f"(c[0]), "+f"(c[1]), "+f"(c[2]), "+f"(c[3])
        : "r"(a[0]), "r"(a[1]), "r"(a[2]), "r"(a[3]), "r"(b0), "r"(b1));
}

// ---------------- HMMA GEMM core (1-pass): C = act(A @ W^T + bias) ----------
// Tile 128x128, k-chunk 32, 3-stage cp.async pipeline, 2 CTAs/SM.
// (round-8/14/16 empirical optimum; classic launch)
#define RSTRIDE 80                 // bytes per 32-half row
#define TILE_SM (128*RSTRIDE)      // 10240 bytes per [128][32] tile
#define NKCH (KDIM/32)             // 32 k-chunks
#define NSTG 3
#define STGB (2*TILE_SM)
#define SMEM_G (NSTG*STGB)         // 61440 -> 2 CTAs/SM

template<int OUT16>
__device__ __forceinline__ void gemm_core(
    const __half* __restrict__ A, const __half* __restrict__ W,
    const float* __restrict__ bias, void* __restrict__ Cv,
    int act, char* smem)
{
    const uint32_t sb = s2u(smem);
    const int tid  = threadIdx.x;
    const int warp = tid >> 5, lane = tid & 31;
    const int wm = warp & 3, wn = warp >> 2;
    const int bm = blockIdx.y * 128, bn = blockIdx.x * 128;

    const int lrow = tid >> 1;
    const int lc   = (tid & 1) * 2;

    const __half* gA = A + (size_t)(bm + lrow) * KDIM + lc * 8;
    const __half* gB = W + (size_t)(bn + lrow) * KDIM + lc * 8;
    const uint32_t dofs = lrow * RSTRIDE + lc * 16;

    float acc[2][8][4];
#pragma unroll
    for (int i = 0; i < 2; i++)
#pragma unroll
        for (int j = 0; j < 8; j++)
#pragma unroll
            for (int q = 0; q < 4; q++) acc[i][j][q] = 0.f;

#define ISSUE(kt, s) do {                                   \
        uint32_t st_ = sb + (s) * STGB + dofs;              \
        int ko_ = (kt) * 32;                                \
        cpa16(st_,                gA + ko_);                \
        cpa16(st_ + 16,           gA + ko_ + 8);            \
        cpa16(st_ + TILE_SM,      gB + ko_);                \
        cpa16(st_ + TILE_SM + 16, gB + ko_ + 8);            \
    } while (0)

#pragma unroll
    for (int s = 0; s < NSTG - 1; s++) { ISSUE(s, s); cp_commit(); }

    const int lm = lane & 15, lh = lane >> 4;

    for (int kt = 0; kt < NKCH; kt++) {
        cp_waitg<NSTG - 2>();
        __syncthreads();
        if (kt + NSTG - 1 < NKCH) ISSUE(kt + NSTG - 1, (kt + NSTG - 1) % NSTG);
        cp_commit();

        const uint32_t st = sb + (kt % NSTG) * STGB;
#pragma unroll
        for (int kk = 0; kk < 2; kk++) {
            const uint32_t kcol = kk * 32 + lh * 16;
            uint32_t ah[2][4], bh[4][4];
#pragma unroll
            for (int mt = 0; mt < 2; mt++) {
                uint32_t r = (uint32_t)(wm * 32 + mt * 16 + lm);
                ldm4(ah[mt], st + r * RSTRIDE + kcol);
            }
#pragma unroll
            for (int g = 0; g < 4; g++) {
                uint32_t r = (uint32_t)(wn * 64 + g * 16 + lm);
                ldm4(bh[g], st + TILE_SM + r * RSTRIDE + kcol);
            }
#pragma unroll
            for (int mt = 0; mt < 2; mt++)
#pragma unroll
                for (int g = 0; g < 4; g++) {
                    mma16816(acc[mt][2*g],   ah[mt], bh[g][0], bh[g][2]);
                    mma16816(acc[mt][2*g+1], ah[mt], bh[g][1], bh[g][3]);
                }
        }
    }
#undef ISSUE

#pragma unroll
    for (int mt = 0; mt < 2; mt++) {
        const int row0 = bm + wm * 32 + mt * 16 + (lane >> 2);
#pragma unroll
        for (int ng = 0; ng < 8; ng++) {
            const int col = bn + wn * 64 + ng * 8 + 2 * (lane & 3);
            const float b0 = bias[col], b1 = bias[col + 1];
            float2 v0, v1;
            v0.x = acc[mt][ng][0] + b0;  v0.y = acc[mt][ng][1] + b1;
            v1.x = acc[mt][ng][2] + b0;  v1.y = acc[mt][ng][3] + b1;
            if (act) {
                v0.x = v0.x > 0.f ? v0.x + 1.f : __expf(v0.x);
                v0.y = v0.y > 0.f ? v0.y + 1.f : __expf(v0.y);
                v1.x = v1.x > 0.f ? v1.x + 1.f : __expf(v1.x);
                v1.y = v1.y > 0.f ? v1.y + 1.f : __expf(v1.y);
            }
            if (OUT16) {
                __half* C = (__half*)Cv;
                *(__half2*)&C[(size_t)row0 * NCOL + col] =
                    __halves2half2(__float2half(v0.x), __float2half(v0.y));
                *(__half2*)&C[(size_t)(row0 + 8) * NCOL + col] =
                    __halves2half2(__float2half(v1.x), __float2half(v1.y));
            } else {
                float* C = (float*)Cv;
                *(float2*)&C[(size_t)row0 * NCOL + col]       = v0;
                *(float2*)&C[(size_t)(row0 + 8) * NCOL + col] = v1;
            }
        }
    }
}

__global__ void __launch_bounds__(256, 2) gemm_qkv(
    const __half* __restrict__ Xin, const __half* __restrict__ Wt,
    const float* __restrict__ bq, const float* __restrict__ bk, const float* __restrict__ bv,
    __half* __restrict__ Qh, __half* __restrict__ Kh, __half* __restrict__ Vh)
{
    extern __shared__ __align__(128) char smem[];
    const int z = blockIdx.z;
    const __half* A = Xin + (size_t)z * Mrows * KDIM;
    const __half* W = Wt  + (size_t)z * NCOL * KDIM;
    const float* bias = (z == 0) ? bq : (z == 1) ? bk : bv;
    __half* C = (z == 0) ? Qh : (z == 1) ? Kh : Vh;
    gemm_core<1>(A, W, bias, C, (z < 2) ? 1 : 0, smem);
}

__global__ void __launch_bounds__(256, 2) gemm_out(
    const __half* __restrict__ A, const __half* __restrict__ W,
    const float* __restrict__ bias, float* __restrict__ C)
{
    extern __shared__ __align__(128) char smem[];
    gemm_core<0>(A, W, bias, C, 0, smem);
}

// ---------------- merged prep: weight transpose+fp16  AND  input fp32->fp16 -
// blocks [0, 4096): wsplit tiles; blocks [4096, 53248): aconv float4 chunks
__global__ void __launch_bounds__(256) prep_all(
    const float* __restrict__ W0, const float* __restrict__ W1,
    const float* __restrict__ W2, const float* __restrict__ W3,
    __half* __restrict__ Wdst,
    const float* __restrict__ q, const float* __restrict__ k,
    const float* __restrict__ v, __half* __restrict__ Xin)
{
    const int bid = blockIdx.x;
    if (bid < 4096) {
        const int wsel = bid >> 10;
        const int rr   = bid & 1023;
        const int n0 = (rr & 31) * 32, k0 = (rr >> 5) * 32;
        const float* W = (wsel == 0) ? W0 : (wsel == 1) ? W1 : (wsel == 2) ? W2 : W3;
        __half* thi = Wdst + (size_t)wsel * NCOL * KDIM;

        __shared__ float tile[32][33];
        const int tx = threadIdx.x & 31, ty = threadIdx.x >> 5;
#pragma unroll
        for (int r = ty; r < 32; r += 8)
            tile[r][tx] = W[(size_t)(k0 + r) * NCOL + n0 + tx];
        __syncthreads();
#pragma unroll
        for (int r = ty; r < 32; r += 8)
            thi[(size_t)(n0 + r) * KDIM + k0 + tx] = __float2half(tile[tx][r]);
    } else {
        const int n4 = Mrows * KDIM / 4;          // 4194304 float4s per input
        const int b2 = bid - 4096;
        const int z  = b2 >> 14;                  // 16384 blocks per input
        const int i  = (b2 & 16383) * 256 + threadIdx.x;
        if (i >= n4) return;
        const float* src = (z == 0) ? q : (z == 1) ? k : v;
        __half* d = Xin + (size_t)z * Mrows * KDIM;
        float4 val = ((const float4*)src)[i];
        __half2* H = (__half2*)d;
        H[2*i]   = __halves2half2(__float2half(val.x), __float2half(val.y));
        H[2*i+1] = __halves2half2(__float2half(val.z), __float2half(val.w));
    }
}

// ---------------- kv via tensor cores: kv[dv,dk] = sum_t V[t,dv] K[t,dk] ----
#define KVROW 144
#define KVTILE (32*KVROW)          // 4608 bytes per 32x64 fp16 tile

__global__ void __launch_bounds__(128) kv_mma(const __half* __restrict__ Kq,
                                              const __half* __restrict__ Vq,
                                              float* __restrict__ kvp, float* __restrict__ ksp)
{
    __shared__ __align__(16) char sm[2 * 2 * KVTILE];   // [stage][K,V]
    const uint32_t sb = s2u(sm);
    const int bh = blockIdx.x, sp = blockIdx.y;
    const int b = bh >> 4, hd = bh & 15;
    const int tid = threadIdx.x, warp = tid >> 5, lane = tid & 31;

    const __half* Kb = Kq + ((size_t)b * Tt + sp * TSEG) * NCOL + hd * DKk;
    const __half* Vb = Vq + ((size_t)b * Tt + sp * TSEG) * NCOL + hd * DVv;

    float acc[8][4];
#pragma unroll
    for (int j = 0; j < 8; j++)
#pragma unroll
        for (int q = 0; q < 4; q++) acc[j][q] = 0.f;
    float ks = 0.f;

#define KVISSUE(t0, s) do {                                            \
        uint32_t base_ = sb + (s) * (2 * KVTILE);                      \
        _Pragma("unroll")                                              \
        for (int p = 0; p < 2; p++) {                                  \
            int idx_ = tid + p * 128;                                  \
            int r_ = idx_ >> 3, cb_ = idx_ & 7;                        \
            cpa16(base_ + r_ * KVROW + cb_ * 16,                       \
                  Kb + (size_t)((t0) + r_) * NCOL + cb_ * 8);          \
            cpa16(base_ + KVTILE + r_ * KVROW + cb_ * 16,              \
                  Vb + (size_t)((t0) + r_) * NCOL + cb_ * 8);          \
        }                                                              \
    } while (0)

    const int NT = TSEG / 32;   // 8
    KVISSUE(0, 0);  cp_commit();
    KVISSUE(32, 1); cp_commit();

    for (int i = 0; i < NT; i++) {
        if (i == NT - 1) cp_waitg<0>(); else cp_waitg<1>();
        __syncthreads();

        const int s = i & 1;
        const uint32_t Kst = sb + s * (2 * KVTILE);
        const uint32_t Vst = Kst + KVTILE;
#pragma unroll
        for (int kk = 0; kk < 2; kk++) {
            const uint32_t rowoff = (kk * 16 + (lane & 15)) * KVROW + (lane >> 4) * 16;
            uint32_t ar[4];
            ldm4t(ar, Vst + rowoff + warp * 32);          // A = V^T (m=dv,k=t)
            uint32_t a2[4] = { ar[0], ar[2], ar[1], ar[3] };
#pragma unroll
            for (int g = 0; g < 4; g++) {
                uint32_t br[4];
                ldm4t(br, Kst + rowoff + g * 32);          // B = K^T (n=dk,k=t)
                mma16816(acc[2*g],   a2, br[0], br[1]);
                mma16816(acc[2*g+1], a2, br[2], br[3]);
            }
        }
        if (tid < 64) {
#pragma unroll
            for (int t = 0; t < 32; t++)
                ks += __half2float(*(const __half*)(sm + s * (2 * KVTILE) + t * KVROW + tid * 2));
        }
        __syncthreads();
        if (i + 2 < NT) { KVISSUE((i + 2) * 32, s); cp_commit(); }
    }
#undef KVISSUE

    float* o = kvp + (size_t)(sp * 64 + bh) * (DVv * DKk);
    const int r = warp * 16 + (lane >> 2);
    const int c = 2 * (lane & 3);
#pragma unroll
    for (int j = 0; j < 8; j++) {
        const int n0 = (j >> 1) * 16 + (j & 1) * 8 + c;
        float2 lo; lo.x = acc[j][0]; lo.y = acc[j][1];
        float2 hi; hi.x = acc[j][2]; hi.y = acc[j][3];
        *(float2*)&o[r * DKk + n0]       = lo;
        *(float2*)&o[(r + 8) * DKk + n0] = hi;
    }
    if (tid < 64) ksp[(sp * 64 + bh) * DKk + tid] = ks;
}

// reduce partials -> fp16 kv + fp32 ksum. grid (64, 16): one kv element per
// thread (same 16-way per-element sum order -> bitwise-identical output),
// 1024 CTAs for latency hiding.
__global__ void __launch_bounds__(256) kv_reduce(const float* __restrict__ kvp, const float* __restrict__ ksp,
                                                 __half* __restrict__ kvh, float* __restrict__ ksum)
{
    const int bh = blockIdx.x, tid = threadIdx.x;
    const int i = blockIdx.y * 256 + tid;
    {
        float s = 0.f;
#pragma unroll
        for (int y = 0; y < KVSPLIT; y++) s += kvp[(size_t)(y * 64 + bh) * (DVv * DKk) + i];
        kvh[(size_t)bh * (DVv * DKk) + i] = __float2half(s);
    }
    if (blockIdx.y == 0 && tid < DKk) {
        float s = 0.f;
#pragma unroll
        for (int y = 0; y < KVSPLIT; y++) s += ksp[(y * 64 + bh) * DKk + tid];
        ksum[bh * DKk + tid] = s;
    }
}

// ---------------- attn via tensor cores: attn[t,dv] = nrm * Q[t,:] . kv[dv,:]
__global__ void __launch_bounds__(128) attn_mma(
    const __half* __restrict__ Qq, const __half* __restrict__ kvh,
    const float* __restrict__ ksum, __half* __restrict__ aout)
{
    __shared__ __align__(16) __half Qs[128 * 72];
    __shared__ __align__(16) __half Bs[64 * 72];
    __shared__ float kss[64];
    __shared__ float nrm[128];

    const int bh = blockIdx.x;
    const int b = bh >> 4, hd = bh & 15;
    const int t0 = blockIdx.y * 128;
    const int tid = threadIdx.x, warp = tid >> 5, lane = tid & 31;

    const __half* Qb = Qq + ((size_t)(b * Tt + t0)) * NCOL + hd * DKk;
#pragma unroll
    for (int p = 0; p < 8; p++) {
        int idx = tid + p * 128;
        int r = idx >> 3, cb = idx & 7;
        *(uint4*)&Qs[r * 72 + cb * 8] = *(const uint4*)&Qb[(size_t)r * NCOL + cb * 8];
    }
    const __half* kb = kvh + (size_t)bh * (DVv * DKk);
#pragma unroll
    for (int p = 0; p < 4; p++) {
        int idx = tid + p * 128;
        int r = idx >> 3, cb = idx & 7;
        *(uint4*)&Bs[r * 72 + cb * 8] = *(const uint4*)&kb[r * DKk + cb * 8];
    }
    if (tid < 64) kss[tid] = ksum[bh * DKk + tid];
    __syncthreads();

    {
        float s = 0.f;
#pragma unroll
        for (int d = 0; d < 64; d++) s += __half2float(Qs[tid * 72 + d]) * kss[d];
        nrm[tid] = 1.f / (s + EPSF);
    }

    const uint32_t sq = s2u(Qs), sbv = s2u(Bs);
    float acc[2][8][4];
#pragma unroll
    for (int i = 0; i < 2; i++)
#pragma unroll
        for (int j = 0; j < 8; j++)
#pragma unroll
            for (int q = 0; q < 4; q++) acc[i][j][q] = 0.f;

#pragma unroll
    for (int k0 = 0; k0 < 64; k0 += 16) {
        const uint32_t coloff = (k0 + (lane >> 4) * 8) * 2;
        uint32_t a[2][4];
#pragma unroll
        for (int mt = 0; mt < 2; mt++)
            ldm4(a[mt], sq + (warp * 32 + mt * 16 + (lane & 15)) * 144 + coloff);
#pragma unroll
        for (int g = 0; g < 4; g++) {
            uint32_t br[4];
            ldm4(br, sbv + (g * 16 + (lane & 15)) * 144 + coloff);
#pragma unroll
            for (int mt = 0; mt < 2; mt++) {
                mma16816(acc[mt][2*g],   a[mt], br[0], br[2]);
                mma16816(acc[mt][2*g+1], a[mt], br[1], br[3]);
            }
        }
    }
    __syncthreads();

#pragma unroll
    for (int mt = 0; mt < 2; mt++) {
        const int r = warp * 32 + mt * 16 + (lane >> 2);
        const float n0r = nrm[r], n1r = nrm[r + 8];
        const size_t row0 = ((size_t)(b * Tt + t0 + r)) * NCOL + hd * DVv;
        const size_t row1 = row0 + 8 * NCOL;
#pragma unroll
        for (int j = 0; j < 8; j++) {
            const int n0 = (j >> 1) * 16 + (j & 1) * 8 + 2 * (lane & 3);
            *(__half2*)&aout[row0 + n0] = __halves2half2(
                __float2half(acc[mt][j][0] * n0r), __float2half(acc[mt][j][1] * n0r));
            *(__half2*)&aout[row1 + n0] = __halves2half2(
                __float2half(acc[mt][j][2] * n1r), __float2half(acc[mt][j][3] * n1r));
        }
    }
}

// ---------------- host ----------------
extern "C" void kernel_launch(void* const* d_in, const int* in_sizes, int n_in,
                              void* d_out, int out_size)
{
    (void)in_sizes; (void)n_in; (void)out_size;
    const float* query = (const float*)d_in[0];
    const float* key   = (const float*)d_in[1];
    const float* value = (const float*)d_in[2];
    const float* Wq    = (const float*)d_in[3];
    const float* bq    = (const float*)d_in[4];
    const float* Wk    = (const float*)d_in[5];
    const float* bk    = (const float*)d_in[6];
    const float* Wv    = (const float*)d_in[7];
    const float* bv    = (const float*)d_in[8];
    const float* Wo    = (const float*)d_in[9];
    const float* bo    = (const float*)d_in[10];
    float* out = (float*)d_out;

    __half *Xin, *Qh, *Kh, *Vh, *At, *Wt, *kvh;
    float *kvpp, *kspp, *kss;
    cudaGetSymbolAddress((void**)&Xin, g_Xin);
    cudaGetSymbolAddress((void**)&Qh,  g_Qh);
    cudaGetSymbolAddress((void**)&Kh,  g_Kh);
    cudaGetSymbolAddress((void**)&Vh,  g_Vh);
    cudaGetSymbolAddress((void**)&At,  g_At);
    cudaGetSymbolAddress((void**)&Wt,  g_Whi);
    cudaGetSymbolAddress((void**)&kvh, g_kvh);
    cudaGetSymbolAddress((void**)&kvpp, g_kvp);
    cudaGetSymbolAddress((void**)&kspp, g_ksp);
    cudaGetSymbolAddress((void**)&kss,  g_ksum);

    cudaFuncSetAttribute(gemm_qkv, cudaFuncAttributeMaxDynamicSharedMemorySize, SMEM_G);
    cudaFuncSetAttribute(gemm_out, cudaFuncAttributeMaxDynamicSharedMemorySize, SMEM_G);

    const size_t WSZ = (size_t)NCOL * KDIM;

    // merged prep: 4096 wsplit blocks + 3*16384 aconv blocks (one launch)
    prep_all<<<4096 + 3 * 16384, 256>>>(Wq, Wk, Wv, Wo, Wt, query, key, value, Xin);

    // QKV projections (classic launch — measured optimum)
    gemm_qkv<<<dim3(NCOL / 128, Mrows / 128, 3), 256, SMEM_G>>>(
        Xin, Wt, bq, bk, bv, Qh, Kh, Vh);

    kv_mma<<<dim3(64, KVSPLIT), 128>>>(Kh, Vh, kvpp, kspp);
    kv_reduce<<<dim3(64, 16), 256>>>(kvpp, kspp, kvh, kss);
    attn_mma<<<dim3(64, Tt / 128), 128>>>(Qh, kvh, kss, At);

    gemm_out<<<dim3(NCOL / 128, Mrows / 128), 256, SMEM_G>>>(At, Wt + 3 * WSZ, bo, out);
}